// round 14
// baseline (speedup 1.0000x reference)
#include <cuda_runtime.h>
#include <cuda_fp16.h>
#include <cstdint>

#define BSZ 16
#define NPIX 1024
#define SCALE_ATT 0.17677669529663687f

// ---------------- static scratch ----------------
__device__ __align__(16) __half g_x16[BSZ * 512 * NPIX];   // input x fp16
__device__ __align__(16) __half g_c16[BSZ * 512 * NPIX];   // cat [a|bb] fp16
__device__ __align__(16) __half g_t16[BSZ * 512 * NPIX];   // qkv / ffn1 fp16
__device__ __align__(16) __half g_a16[BSZ * 256 * NPIX];   // xa fp16 (attn out, then +pe)
__device__ __align__(16) float g_bbf [BSZ * 256 * NPIX];   // bb chain f32 (cm)
__device__ __align__(16) __half g_wh[983040];

__device__ __forceinline__ float silu_f(float v) {
    return v / (1.0f + __expf(-v));
}

__device__ __forceinline__ uint32_t s2u(const void* p) {
    uint32_t a;
    asm("{ .reg .u64 t; cvta.to.shared.u64 t, %1; cvt.u32.u64 %0, t; }" : "=r"(a) : "l"(p));
    return a;
}

__device__ __forceinline__ void cpa(uint32_t saddr, const void* g) {
    asm volatile("cp.async.cg.shared.global [%0], [%1], 16;" :: "r"(saddr), "l"(g));
}

__device__ __forceinline__ void ldsm_x4(uint32_t* r, uint32_t addr) {
    asm volatile("ldmatrix.sync.aligned.m8n8.x4.shared.b16 {%0,%1,%2,%3}, [%4];"
                 : "=r"(r[0]), "=r"(r[1]), "=r"(r[2]), "=r"(r[3]) : "r"(addr));
}

__device__ __forceinline__ void ldsm_x4t(uint32_t* r, uint32_t addr) {
    asm volatile("ldmatrix.sync.aligned.m8n8.x4.trans.shared.b16 {%0,%1,%2,%3}, [%4];"
                 : "=r"(r[0]), "=r"(r[1]), "=r"(r[2]), "=r"(r[3]) : "r"(addr));
}

__device__ __forceinline__ void mma_f16(float* c, const uint32_t* a, const uint32_t* b) {
    asm volatile(
        "mma.sync.aligned.m16n8k16.row.col.f32.f16.f16.f32 "
        "{%0,%1,%2,%3}, {%4,%5,%6,%7}, {%8,%9}, {%0,%1,%2,%3};\n"
        : "+f"(c[0]), "+f"(c[1]), "+f"(c[2]), "+f"(c[3])
        : "r"(a[0]), "r"(a[1]), "r"(a[2]), "r"(a[3]), "r"(b[0]), "r"(b[1]));
}

// ---------------- fp16 tensor-core GEMM (plain W/X, BK=64, 3-stage) ----------------
#define A_BYTES (128 * 144)                  // 18432 (64 halfs + 16B pad per row)
#define B_BYTES (64 * 256)                   // 16384
#define STAGE_B (A_BYTES + B_BYTES)          // 34816
#define GSMEM   (3 * STAGE_B)                // 104448

__global__ __launch_bounds__(256, 2) void gemm_f16(
    const __half* __restrict__ X, long xbs, int K,
    const __half* __restrict__ W,
    const float* __restrict__ sc, const float* __restrict__ bi,
    const float* __restrict__ res, long rbs,
    float* __restrict__ outf, long ofbs, int ofoff,
    __half* __restrict__ oh, long ohbs,
    int act)
{
    extern __shared__ __align__(16) char smem[];
    const uint32_t sb = s2u(smem);
    const int tid  = threadIdx.x;
    const int warp = tid >> 5;
    const int lane = tid & 31;
    const int g    = lane >> 2;
    const int tig  = lane & 3;
    const int wm   = warp >> 2;
    const int wn   = warp & 3;
    const int b  = blockIdx.z;
    const int n0 = blockIdx.x * 128;
    const int m0 = blockIdx.y * 128;

    const __half* Xb = X + (size_t)b * xbs;

    float acc[4][4][4];
#pragma unroll
    for (int f = 0; f < 4; f++)
#pragma unroll
        for (int fn = 0; fn < 4; fn++)
#pragma unroll
            for (int q = 0; q < 4; q++) acc[f][fn][q] = 0.0f;

    auto issue = [&](int c, int buf) {
        const uint32_t st = sb + buf * STAGE_B;
        const int k0 = c * 64;
        // A: 128 rows x 8 16B-chunks (64 halfs/row), 4 per thread
#pragma unroll
        for (int r = 0; r < 4; r++) {
            const int ca  = tid + 256 * r;
            const int row = ca >> 3, kc16 = ca & 7;
            cpa(st + row * 144 + kc16 * 16, W + (size_t)(m0 + row) * K + k0 + kc16 * 8);
        }
        // B: 64 k-rows x 16 chunks, 4 per thread
#pragma unroll
        for (int r = 0; r < 4; r++) {
            const int ca = tid + 256 * r;
            const int kr = ca >> 4, nc2 = ca & 15;
            cpa(st + A_BYTES + kr * 256 + (((uint32_t)(nc2 ^ (kr & 7))) << 4),
                Xb + (size_t)(k0 + kr) * NPIX + n0 + nc2 * 8);
        }
        asm volatile("cp.async.commit_group;");
    };

    const int nc = K >> 6;
    issue(0, 0);
    if (nc > 1) issue(1, 1);

    const int arow  = wm * 64 + (lane & 15);
    const int akoff = (lane >> 4) * 16;
    const int blk16 = lane & 15;
    const int ncsel = lane >> 4;

    int buf = 0;
    for (int c = 0; c < nc; c++) {
        if (c + 1 < nc) asm volatile("cp.async.wait_group 1;");
        else            asm volatile("cp.async.wait_group 0;");
        __syncthreads();

        const uint32_t st = sb + buf * STAGE_B;

#pragma unroll
        for (int kc = 0; kc < 4; kc++) {
            uint32_t a_h[4][4];
#pragma unroll
            for (int f = 0; f < 4; f++)
                ldsm_x4(a_h[f], st + (uint32_t)(arow + f * 16) * 144 + kc * 32 + akoff);
#pragma unroll
            for (int fnp = 0; fnp < 2; fnp++) {
                const int ncb = wn * 4 + fnp * 2 + ncsel;
                const uint32_t bd = st + A_BYTES + (uint32_t)(kc * 16 + blk16) * 256 +
                                    (((uint32_t)(ncb ^ (blk16 & 7))) << 4);
                uint32_t b4[4];
                ldsm_x4t(b4, bd);
#pragma unroll
                for (int f = 0; f < 4; f++) {
                    mma_f16(acc[f][2 * fnp],     a_h[f], b4);
                    mma_f16(acc[f][2 * fnp + 1], a_h[f], b4 + 2);
                }
            }
            if (kc == 0 && c + 2 < nc) {
                int nb = buf + 2; if (nb >= 3) nb -= 3;
                issue(c + 2, nb);
            }
        }
        if (++buf == 3) buf = 0;
    }

    const bool do_f = (outf != nullptr) && (m0 >= ofoff);
#pragma unroll
    for (int f = 0; f < 4; f++) {
        const int m = m0 + wm * 64 + f * 16 + g;
        const float s0 = sc[m],     b0 = bi[m];
        const float s1 = sc[m + 8], b1 = bi[m + 8];
#pragma unroll
        for (int fn = 0; fn < 4; fn++) {
            const int n = n0 + wn * 32 + fn * 8 + 2 * tig;
            float v00 = acc[f][fn][0] * s0 + b0;
            float v01 = acc[f][fn][1] * s0 + b0;
            float v10 = acc[f][fn][2] * s1 + b1;
            float v11 = acc[f][fn][3] * s1 + b1;
            if (res) {
                float2 ra = *(const float2*)(res + (size_t)b * rbs + (size_t)m * NPIX + n);
                float2 rb = *(const float2*)(res + (size_t)b * rbs + (size_t)(m + 8) * NPIX + n);
                v00 += ra.x; v01 += ra.y; v10 += rb.x; v11 += rb.y;
            }
            if (act) {
                v00 = silu_f(v00); v01 = silu_f(v01);
                v10 = silu_f(v10); v11 = silu_f(v11);
            }
            if (do_f) {
                const int mo = m - ofoff;
                *(float2*)(outf + (size_t)b * ofbs + (size_t)mo * NPIX + n) = make_float2(v00, v01);
                *(float2*)(outf + (size_t)b * ofbs + (size_t)(mo + 8) * NPIX + n) = make_float2(v10, v11);
            }
            if (oh) {
                *(__half2*)(oh + (size_t)b * ohbs + (size_t)m * NPIX + n) =
                    __halves2half2(__float2half_rn(v00), __float2half_rn(v01));
                *(__half2*)(oh + (size_t)b * ohbs + (size_t)(m + 8) * NPIX + n) =
                    __halves2half2(__float2half_rn(v10), __float2half_rn(v11));
            }
        }
    }
}

// ---------------- converts ----------------
__global__ void cvt16(const float4* __restrict__ src, uint2* __restrict__ dst, int n4)
{
    int i = blockIdx.x * 256 + threadIdx.x;
    if (i < n4) {
        float4 v = src[i];
        __half h[4];
        h[0] = __float2half_rn(v.x); h[1] = __float2half_rn(v.y);
        h[2] = __float2half_rn(v.z); h[3] = __float2half_rn(v.w);
        dst[i] = *(uint2*)h;
    }
}

__global__ void wcvt_all(
    const float* __restrict__ W0, const float* __restrict__ W1,
    const float* __restrict__ W2, const float* __restrict__ W3,
    const float* __restrict__ W4, const float* __restrict__ W5,
    __half* __restrict__ wh)
{
    int blk = blockIdx.x;
    const float* src; int off;
    if      (blk < 256) { src = W0; off = 0;      }
    else if (blk < 384) { src = W1; off = 262144; blk -= 256; }
    else if (blk < 448) { src = W2; off = 393216; blk -= 384; }
    else if (blk < 576) { src = W3; off = 458752; blk -= 448; }
    else if (blk < 704) { src = W4; off = 589824; blk -= 576; }
    else                { src = W5; off = 720896; blk -= 704; }
    int i = blk * 256 + threadIdx.x;
    float4 v = ((const float4*)src)[i];
    __half h[4];
    h[0] = __float2half_rn(v.x); h[1] = __float2half_rn(v.y);
    h[2] = __float2half_rn(v.z); h[3] = __float2half_rn(v.w);
    ((uint2*)(wh + off))[i] = *(uint2*)h;
}

// ---------------- tensor-core flash attention (FA2, h2exp, fp16 out) ----------------
#define RS 272
#define OFF_Q 0
#define OFF_K 8704
#define KBUF 8704
#define OFF_V 26112
#define VBUF 17408
#define ASMEM 60928

__global__ __launch_bounds__(256, 2) void attn_mma(
    const __half* __restrict__ qv, __half* __restrict__ xa)
{
    extern __shared__ __align__(16) char smn[];
    const uint32_t sb = s2u(smn);

    const int tid = threadIdx.x;
    const int warp = tid >> 5, lane = tid & 31;
    const int g = lane >> 2, tig = lane & 3;
    const int bh = blockIdx.y;
    const int r0 = blockIdx.x * 128;
    const size_t cb = (size_t)bh * 128 * NPIX;

#pragma unroll
    for (int i = 0; i < 2; i++) {
        int idx = i * 256 + tid;
        int row = idx >> 4, ch = idx & 15;
        cpa(sb + OFF_Q + row * RS + ch * 16, qv + cb + (size_t)row * NPIX + r0 + ch * 8);
    }
    auto loadK = [&](int mt, int kb) {
#pragma unroll
        for (int i = 0; i < 2; i++) {
            int idx = i * 256 + tid;
            int row = idx >> 4, ch = idx & 15;
            cpa(sb + OFF_K + kb * KBUF + row * RS + ch * 16,
                qv + cb + (size_t)(32 + row) * NPIX + mt * 128 + ch * 8);
        }
    };
    auto loadV = [&](int mt, int vb) {
#pragma unroll
        for (int i = 0; i < 4; i++) {
            int idx = i * 256 + tid;
            int row = (idx >> 4) & 63, ch = idx & 15;
            cpa(sb + OFF_V + vb * VBUF + row * RS + ch * 16,
                qv + cb + (size_t)(64 + row) * NPIX + mt * 128 + ch * 8);
        }
    };
    loadK(0, 0); loadV(0, 0);
    asm volatile("cp.async.commit_group;");

    float m_s[2] = {-1e30f, -1e30f}, l_s[2] = {0.f, 0.f};
    float accO[8][4];
#pragma unroll
    for (int nt = 0; nt < 8; nt++)
#pragma unroll
        for (int q = 0; q < 4; q++) accO[nt][q] = 0.f;

    const int krow = (lane & 7) + ((lane >> 4) << 3);
    const int mcol = ((lane >> 3) & 1) * 8;
    const int ncsel = lane >> 4;
    const int vrow = ((lane >> 4) << 3) + (lane & 7);
    const int vch  = ((lane >> 3) & 1) * 8;

    uint32_t qf[2][4];

    for (int mt = 0; mt < 8; mt++) {
        asm volatile("cp.async.wait_group 0;");
        __syncthreads();
        const int kb = mt & 1, vb = mt & 1;

        if (mt + 1 < 8) {
            loadK(mt + 1, kb ^ 1);
            loadV(mt + 1, vb ^ 1);
        }
        asm volatile("cp.async.commit_group;");

        if (mt == 0) {
#pragma unroll
            for (int kc = 0; kc < 2; kc++)
                ldsm_x4t(qf[kc], sb + OFF_Q + (kc * 16 + krow) * RS +
                                 (warp * 16 + mcol) * 2);
        }

        float accS[16][4];
#pragma unroll
        for (int fn = 0; fn < 16; fn++)
#pragma unroll
            for (int q = 0; q < 4; q++) accS[fn][q] = 0.f;

#pragma unroll
        for (int kc = 0; kc < 2; kc++) {
#pragma unroll
            for (int fnp = 0; fnp < 8; fnp++) {
                const int ncb = fnp * 2 + ncsel;
                uint32_t bd = sb + OFF_K + kb * KBUF +
                              (uint32_t)(kc * 16 + (lane & 15)) * RS + ncb * 16;
                uint32_t k4[4];
                ldsm_x4t(k4, bd);
                mma_f16(accS[2 * fnp],     qf[kc], k4);
                mma_f16(accS[2 * fnp + 1], qf[kc], k4 + 2);
            }
        }

        float mx0 = -1e30f, mx1 = -1e30f;
#pragma unroll
        for (int fn = 0; fn < 16; fn++) {
            mx0 = fmaxf(mx0, fmaxf(accS[fn][0], accS[fn][1]));
            mx1 = fmaxf(mx1, fmaxf(accS[fn][2], accS[fn][3]));
        }
        mx0 = fmaxf(mx0, __shfl_xor_sync(0xffffffffu, mx0, 1));
        mx0 = fmaxf(mx0, __shfl_xor_sync(0xffffffffu, mx0, 2));
        mx1 = fmaxf(mx1, __shfl_xor_sync(0xffffffffu, mx1, 1));
        mx1 = fmaxf(mx1, __shfl_xor_sync(0xffffffffu, mx1, 2));
        mx0 *= SCALE_ATT; mx1 *= SCALE_ATT;
        mx0 = fmaxf(mx0, m_s[0]);
        mx1 = fmaxf(mx1, m_s[1]);
        const float sf0 = __expf(m_s[0] - mx0);
        const float sf1 = __expf(m_s[1] - mx1);
        m_s[0] = mx0; m_s[1] = mx1;
        l_s[0] *= sf0; l_s[1] *= sf1;
#pragma unroll
        for (int nt = 0; nt < 8; nt++) {
            accO[nt][0] *= sf0; accO[nt][1] *= sf0;
            accO[nt][2] *= sf1; accO[nt][3] *= sf1;
        }

        float ps0 = 0.f, ps1 = 0.f;
#pragma unroll
        for (int fn = 0; fn < 16; fn++) {
            float t0 = fmaf(accS[fn][0], SCALE_ATT, -mx0);
            float t1 = fmaf(accS[fn][1], SCALE_ATT, -mx0);
            float t2 = fmaf(accS[fn][2], SCALE_ATT, -mx1);
            float t3 = fmaf(accS[fn][3], SCALE_ATT, -mx1);
            __half2 ha = h2exp(__floats2half2_rn(t0, t1));
            __half2 hb = h2exp(__floats2half2_rn(t2, t3));
            float2 fa = __half22float2(ha);
            float2 fb = __half22float2(hb);
            ps0 += fa.x + fa.y; ps1 += fb.x + fb.y;
            accS[fn][0] = __uint_as_float(*(uint32_t*)&ha);
            accS[fn][2] = __uint_as_float(*(uint32_t*)&hb);
        }
        ps0 += __shfl_xor_sync(0xffffffffu, ps0, 1);
        ps0 += __shfl_xor_sync(0xffffffffu, ps0, 2);
        ps1 += __shfl_xor_sync(0xffffffffu, ps1, 1);
        ps1 += __shfl_xor_sync(0xffffffffu, ps1, 2);
        l_s[0] += ps0; l_s[1] += ps1;

#pragma unroll
        for (int kc = 0; kc < 8; kc++) {
            uint32_t pa[4];
            pa[0] = __float_as_uint(accS[2 * kc][0]);
            pa[1] = __float_as_uint(accS[2 * kc][2]);
            pa[2] = __float_as_uint(accS[2 * kc + 1][0]);
            pa[3] = __float_as_uint(accS[2 * kc + 1][2]);
#pragma unroll
            for (int ntp = 0; ntp < 4; ntp++) {
                uint32_t bd = sb + OFF_V + vb * VBUF +
                              (uint32_t)(ntp * 16 + vrow) * RS + (kc * 16 + vch) * 2;
                uint32_t v4[4];
                ldsm_x4(v4, bd);
                mma_f16(accO[2 * ntp],     pa, v4);
                mma_f16(accO[2 * ntp + 1], pa, v4 + 2);
            }
        }
    }

    const float il0 = 1.0f / l_s[0], il1 = 1.0f / l_s[1];
    const int r = r0 + warp * 16 + g;
#pragma unroll
    for (int nt = 0; nt < 8; nt++) {
        const int d = nt * 8 + 2 * tig;
        xa[(size_t)(bh * 64 + d) * NPIX + r]         = __float2half_rn(accO[nt][0] * il0);
        xa[(size_t)(bh * 64 + d + 1) * NPIX + r]     = __float2half_rn(accO[nt][1] * il0);
        xa[(size_t)(bh * 64 + d) * NPIX + r + 8]     = __float2half_rn(accO[nt][2] * il1);
        xa[(size_t)(bh * 64 + d + 1) * NPIX + r + 8] = __float2half_rn(accO[nt][3] * il1);
    }
}

// ---------------- depthwise 3x3 PE: 4 channels/block, xa += conv(v) in place ----------------
__global__ __launch_bounds__(256) void dwconv_pe(
    const __half* __restrict__ qv, const float* __restrict__ Wpe,
    const float* __restrict__ s, const float* __restrict__ bi,
    __half* __restrict__ xa)
{
    __shared__ float t[4][34 * 34];
    const int c0 = blockIdx.x * 4;
    const int b  = blockIdx.y;
    const int tid = threadIdx.x;

#pragma unroll
    for (int j = 0; j < 4; j++)
        for (int i = tid; i < 34 * 34; i += 256) t[j][i] = 0.0f;
    __syncthreads();
#pragma unroll
    for (int j = 0; j < 4; j++) {
        const int c = c0 + j;
        const int qc = ((c >> 6) * 128) + 64 + (c & 63);
        const __half* src = qv + ((size_t)b * 512 + qc) * NPIX;
        for (int i = tid; i < NPIX; i += 256) {
            int y = i >> 5, x = i & 31;
            t[j][(y + 1) * 34 + (x + 1)] = __half2float(src[i]);
        }
    }
    __syncthreads();

#pragma unroll
    for (int j = 0; j < 4; j++) {
        const int c = c0 + j;
        float w[9];
#pragma unroll
        for (int i = 0; i < 9; i++) w[i] = Wpe[c * 9 + i];
        const float scv = s[c], bv = bi[c];
        __half* dst = xa + ((size_t)b * 256 + c) * NPIX;
        for (int i = tid; i < NPIX; i += 256) {
            int y = i >> 5, x = i & 31;
            float acc = 0.0f;
#pragma unroll
            for (int ky = 0; ky < 3; ky++)
#pragma unroll
                for (int kx = 0; kx < 3; kx++)
                    acc += w[ky * 3 + kx] * t[j][(y + ky) * 34 + (x + kx)];
            float v = __half2float(dst[i]) + acc * scv + bv;
            dst[i] = __float2half_rn(v);
        }
    }
}

// ---------------- launcher ----------------
extern "C" void kernel_launch(void* const* d_in, const int* in_sizes, int n_in,
                              void* d_out, int out_size)
{
    (void)in_sizes; (void)n_in; (void)out_size;
    const float* x      = (const float*)d_in[0];
    const float* W_cv1  = (const float*)d_in[1];
    const float* s_cv1  = (const float*)d_in[2];
    const float* b_cv1  = (const float*)d_in[3];
    const float* W_qkv  = (const float*)d_in[4];
    const float* s_qkv  = (const float*)d_in[5];
    const float* b_qkv  = (const float*)d_in[6];
    const float* W_proj = (const float*)d_in[7];
    const float* s_proj = (const float*)d_in[8];
    const float* b_proj = (const float*)d_in[9];
    const float* W_pe   = (const float*)d_in[10];
    const float* s_pe   = (const float*)d_in[11];
    const float* b_pe   = (const float*)d_in[12];
    const float* W_ffn1 = (const float*)d_in[13];
    const float* s_ffn1 = (const float*)d_in[14];
    const float* b_ffn1 = (const float*)d_in[15];
    const float* W_ffn2 = (const float*)d_in[16];
    const float* s_ffn2 = (const float*)d_in[17];
    const float* b_ffn2 = (const float*)d_in[18];
    const float* W_cv2  = (const float*)d_in[19];
    const float* s_cv2  = (const float*)d_in[20];
    const float* b_cv2  = (const float*)d_in[21];

    static __half *x16 = nullptr, *c16, *t16, *a16, *wh;
    static float *bbf;
    if (!x16) {
        cudaGetSymbolAddress((void**)&x16, g_x16);
        cudaGetSymbolAddress((void**)&c16, g_c16);
        cudaGetSymbolAddress((void**)&t16, g_t16);
        cudaGetSymbolAddress((void**)&a16, g_a16);
        cudaGetSymbolAddress((void**)&wh,  g_wh);
        cudaGetSymbolAddress((void**)&bbf, g_bbf);
        cudaFuncSetAttribute(attn_mma,
                             cudaFuncAttributeMaxDynamicSharedMemorySize, ASMEM);
        cudaFuncSetAttribute(gemm_f16,
                             cudaFuncAttributeMaxDynamicSharedMemorySize, GSMEM);
    }
    float* out = (float*)d_out;
    const long S512 = 512 * NPIX, S256 = 256 * NPIX;

    const int W_CV1 = 0, W_QKV = 262144, W_PROJ = 393216,
              W_FFN1 = 458752, W_FFN2 = 589824, W_CV2 = 720896;

    // #0: convert x -> fp16
    {
        int n4 = BSZ * 512 * NPIX / 4;
        cvt16<<<(n4 + 255) / 256, 256>>>((const float4*)x, (uint2*)x16, n4);
    }
    // #1: convert all weights -> fp16
    wcvt_all<<<960, 256>>>(W_cv1, W_qkv, W_proj, W_ffn1, W_ffn2, W_cv2, wh);
    // #2: cv1 (SiLU) -> c16 fp16 + bbf f32 for ch>=256
    gemm_f16<<<dim3(8, 4, BSZ), 256, GSMEM>>>(
        x16, S512, 512, wh + W_CV1, s_cv1, b_cv1,
        nullptr, 0, bbf, S256, 256, c16, S512, 1);
    // #3: qkv -> t16 fp16
    gemm_f16<<<dim3(8, 4, BSZ), 256, GSMEM>>>(
        c16 + S256, S512, 256, wh + W_QKV, s_qkv, b_qkv,
        nullptr, 0, nullptr, 0, 1 << 30, t16, S512, 0);
    // #4: flash attention -> a16 (fp16)
    attn_mma<<<dim3(8, 64), 256, ASMEM>>>(t16, a16);
    // #5: PE dwconv: a16 += conv(v) (in place, 4 ch/block)
    dwconv_pe<<<dim3(64, BSZ), 256>>>(t16, W_pe, s_pe, b_pe, a16);
    // #6: proj (+bb residual) -> bbf (in place) + c16 ch256+
    gemm_f16<<<dim3(8, 2, BSZ), 256, GSMEM>>>(
        a16, S256, 256, wh + W_PROJ, s_proj, b_proj,
        bbf, S256, bbf, S256, 0, c16 + S256, S512, 0);
    // #7: ffn1 (SiLU) -> t16
    gemm_f16<<<dim3(8, 4, BSZ), 256, GSMEM>>>(
        c16 + S256, S512, 256, wh + W_FFN1, s_ffn1, b_ffn1,
        nullptr, 0, nullptr, 0, 1 << 30, t16, S512, 1);
    // #8: ffn2 (+bb2 residual) -> c16 ch256+
    gemm_f16<<<dim3(8, 2, BSZ), 256, GSMEM>>>(
        t16, S512, 512, wh + W_FFN2, s_ffn2, b_ffn2,
        bbf, S256, nullptr, 0, 1 << 30, c16 + S256, S512, 0);
    // #9: cv2 (SiLU) -> out
    gemm_f16<<<dim3(8, 4, BSZ), 256, GSMEM>>>(
        c16, S512, 512, wh + W_CV2, s_cv2, b_cv2,
        nullptr, 0, out, S512, 0, nullptr, 0, 1);
}

// round 16
// speedup vs baseline: 1.0157x; 1.0157x over previous
#include <cuda_runtime.h>
#include <cuda_fp16.h>
#include <cstdint>

#define BSZ 16
#define NPIX 1024
#define SCALE_ATT 0.17677669529663687f

// ---------------- static scratch ----------------
__device__ __align__(16) __half g_x16[BSZ * 512 * NPIX];   // input x fp16
__device__ __align__(16) __half g_c16[BSZ * 512 * NPIX];   // cat [a|bb] fp16
__device__ __align__(16) __half g_t16[BSZ * 512 * NPIX];   // qkv / ffn1 fp16
__device__ __align__(16) __half g_a16[BSZ * 256 * NPIX];   // xa fp16 (attn out, then +pe)
__device__ __align__(16) float g_bbf [BSZ * 256 * NPIX];   // bb chain f32 (cm)
__device__ __align__(16) __half g_wh[983040];

__device__ __forceinline__ float silu_f(float v) {
    return v / (1.0f + __expf(-v));
}

__device__ __forceinline__ uint32_t s2u(const void* p) {
    uint32_t a;
    asm("{ .reg .u64 t; cvta.to.shared.u64 t, %1; cvt.u32.u64 %0, t; }" : "=r"(a) : "l"(p));
    return a;
}

__device__ __forceinline__ void cpa(uint32_t saddr, const void* g) {
    asm volatile("cp.async.cg.shared.global [%0], [%1], 16;" :: "r"(saddr), "l"(g));
}

__device__ __forceinline__ void ldsm_x4(uint32_t* r, uint32_t addr) {
    asm volatile("ldmatrix.sync.aligned.m8n8.x4.shared.b16 {%0,%1,%2,%3}, [%4];"
                 : "=r"(r[0]), "=r"(r[1]), "=r"(r[2]), "=r"(r[3]) : "r"(addr));
}

__device__ __forceinline__ void ldsm_x4t(uint32_t* r, uint32_t addr) {
    asm volatile("ldmatrix.sync.aligned.m8n8.x4.trans.shared.b16 {%0,%1,%2,%3}, [%4];"
                 : "=r"(r[0]), "=r"(r[1]), "=r"(r[2]), "=r"(r[3]) : "r"(addr));
}

__device__ __forceinline__ void mma_f16(float* c, const uint32_t* a, const uint32_t* b) {
    asm volatile(
        "mma.sync.aligned.m16n8k16.row.col.f32.f16.f16.f32 "
        "{%0,%1,%2,%3}, {%4,%5,%6,%7}, {%8,%9}, {%0,%1,%2,%3};\n"
        : "+f"(c[0]), "+f"(c[1]), "+f"(c[2]), "+f"(c[3])
        : "r"(a[0]), "r"(a[1]), "r"(a[2]), "r"(a[3]), "r"(b[0]), "r"(b[1]));
}

// ---------------- fp16 tensor-core GEMM (plain W/X, BK=32, 3-stage) ----------------
#define A_BYTES (128 * 80)                   // 10240
#define B_BYTES (32 * 256)                   // 8192
#define STAGE_B (A_BYTES + B_BYTES)          // 18432
#define GSMEM   (3 * STAGE_B)                // 55296

__global__ __launch_bounds__(256, 2) void gemm_f16(
    const __half* __restrict__ X, long xbs, int K,
    const __half* __restrict__ W,
    const float* __restrict__ sc, const float* __restrict__ bi,
    const float* __restrict__ res, long rbs,
    float* __restrict__ outf, long ofbs, int ofoff,
    __half* __restrict__ oh, long ohbs,
    int act)
{
    extern __shared__ __align__(16) char smem[];
    const uint32_t sb = s2u(smem);
    const int tid  = threadIdx.x;
    const int warp = tid >> 5;
    const int lane = tid & 31;
    const int g    = lane >> 2;
    const int tig  = lane & 3;
    const int wm   = warp >> 2;
    const int wn   = warp & 3;
    const int b  = blockIdx.z;
    const int n0 = blockIdx.x * 128;
    const int m0 = blockIdx.y * 128;

    const __half* Xb = X + (size_t)b * xbs;

    float acc[4][4][4];
#pragma unroll
    for (int f = 0; f < 4; f++)
#pragma unroll
        for (int fn = 0; fn < 4; fn++)
#pragma unroll
            for (int q = 0; q < 4; q++) acc[f][fn][q] = 0.0f;

    auto issue = [&](int c, int buf) {
        const uint32_t st = sb + buf * STAGE_B;
        const int k0 = c * 32;
#pragma unroll
        for (int r = 0; r < 2; r++) {
            const int ca  = tid + 256 * r;
            const int row = ca >> 2, kc16 = ca & 3;
            cpa(st + row * 80 + kc16 * 16, W + (size_t)(m0 + row) * K + k0 + kc16 * 8);
        }
#pragma unroll
        for (int r = 0; r < 2; r++) {
            const int ca = tid + 256 * r;
            const int kr = ca >> 4, nc2 = ca & 15;
            cpa(st + A_BYTES + kr * 256 + (((uint32_t)(nc2 ^ (kr & 7))) << 4),
                Xb + (size_t)(k0 + kr) * NPIX + n0 + nc2 * 8);
        }
        asm volatile("cp.async.commit_group;");
    };

    const int nc = K >> 5;
    issue(0, 0);
    if (nc > 1) issue(1, 1);

    const int arow  = wm * 64 + (lane & 15);
    const int akoff = (lane >> 4) * 16;
    const int blk16 = lane & 15;
    const int ncsel = lane >> 4;

    int buf = 0;
    for (int c = 0; c < nc; c++) {
        if (c + 1 < nc) asm volatile("cp.async.wait_group 1;");
        else            asm volatile("cp.async.wait_group 0;");
        __syncthreads();

        const uint32_t st = sb + buf * STAGE_B;

#pragma unroll
        for (int kc = 0; kc < 2; kc++) {
            uint32_t a_h[4][4];
#pragma unroll
            for (int f = 0; f < 4; f++)
                ldsm_x4(a_h[f], st + (uint32_t)(arow + f * 16) * 80 + kc * 32 + akoff);
#pragma unroll
            for (int fnp = 0; fnp < 2; fnp++) {
                const int ncb = wn * 4 + fnp * 2 + ncsel;
                const uint32_t bd = st + A_BYTES + (uint32_t)(kc * 16 + blk16) * 256 +
                                    (((uint32_t)(ncb ^ (blk16 & 7))) << 4);
                uint32_t b4[4];
                ldsm_x4t(b4, bd);
#pragma unroll
                for (int f = 0; f < 4; f++) {
                    mma_f16(acc[f][2 * fnp],     a_h[f], b4);
                    mma_f16(acc[f][2 * fnp + 1], a_h[f], b4 + 2);
                }
            }
            if (kc == 0 && c + 2 < nc) {
                int nb = buf + 2; if (nb >= 3) nb -= 3;
                issue(c + 2, nb);
            }
        }
        if (++buf == 3) buf = 0;
    }

    const bool do_f = (outf != nullptr) && (m0 >= ofoff);
#pragma unroll
    for (int f = 0; f < 4; f++) {
        const int m = m0 + wm * 64 + f * 16 + g;
        const float s0 = sc[m],     b0 = bi[m];
        const float s1 = sc[m + 8], b1 = bi[m + 8];
#pragma unroll
        for (int fn = 0; fn < 4; fn++) {
            const int n = n0 + wn * 32 + fn * 8 + 2 * tig;
            float v00 = acc[f][fn][0] * s0 + b0;
            float v01 = acc[f][fn][1] * s0 + b0;
            float v10 = acc[f][fn][2] * s1 + b1;
            float v11 = acc[f][fn][3] * s1 + b1;
            if (res) {
                float2 ra = *(const float2*)(res + (size_t)b * rbs + (size_t)m * NPIX + n);
                float2 rb = *(const float2*)(res + (size_t)b * rbs + (size_t)(m + 8) * NPIX + n);
                v00 += ra.x; v01 += ra.y; v10 += rb.x; v11 += rb.y;
            }
            if (act) {
                v00 = silu_f(v00); v01 = silu_f(v01);
                v10 = silu_f(v10); v11 = silu_f(v11);
            }
            if (do_f) {
                const int mo = m - ofoff;
                *(float2*)(outf + (size_t)b * ofbs + (size_t)mo * NPIX + n) = make_float2(v00, v01);
                *(float2*)(outf + (size_t)b * ofbs + (size_t)(mo + 8) * NPIX + n) = make_float2(v10, v11);
            }
            if (oh) {
                *(__half2*)(oh + (size_t)b * ohbs + (size_t)m * NPIX + n) =
                    __halves2half2(__float2half_rn(v00), __float2half_rn(v01));
                *(__half2*)(oh + (size_t)b * ohbs + (size_t)(m + 8) * NPIX + n) =
                    __halves2half2(__float2half_rn(v10), __float2half_rn(v11));
            }
        }
    }
}

// ---------------- merged convert: x (8192 blocks) + weights (960 blocks) ----------------
__global__ void cvt_all(
    const float* __restrict__ x,
    const float* __restrict__ W0, const float* __restrict__ W1,
    const float* __restrict__ W2, const float* __restrict__ W3,
    const float* __restrict__ W4, const float* __restrict__ W5,
    __half* __restrict__ x16, __half* __restrict__ wh)
{
    int blk = blockIdx.x;
    const float* src;
    __half* dst;
    if (blk < 8192) {                       // x: 16*512*1024 floats /4 /256 = 8192 blocks
        src = x; dst = x16;
    } else {
        blk -= 8192;
        int off;
        if      (blk < 256) { src = W0; off = 0;      }
        else if (blk < 384) { src = W1; off = 262144; blk -= 256; }
        else if (blk < 448) { src = W2; off = 393216; blk -= 384; }
        else if (blk < 576) { src = W3; off = 458752; blk -= 448; }
        else if (blk < 704) { src = W4; off = 589824; blk -= 576; }
        else                { src = W5; off = 720896; blk -= 704; }
        dst = wh + off;
    }
    int i = blk * 256 + threadIdx.x;
    float4 v = ((const float4*)src)[i];
    __half h[4];
    h[0] = __float2half_rn(v.x); h[1] = __float2half_rn(v.y);
    h[2] = __float2half_rn(v.z); h[3] = __float2half_rn(v.w);
    ((uint2*)dst)[i] = *(uint2*)h;
}

// ---------------- tensor-core flash attention (FA2, h2exp, fp16 out) ----------------
#define RS 272
#define OFF_Q 0
#define OFF_K 8704
#define KBUF 8704
#define OFF_V 26112
#define VBUF 17408
#define ASMEM 60928

__global__ __launch_bounds__(256, 2) void attn_mma(
    const __half* __restrict__ qv, __half* __restrict__ xa)
{
    extern __shared__ __align__(16) char smn[];
    const uint32_t sb = s2u(smn);

    const int tid = threadIdx.x;
    const int warp = tid >> 5, lane = tid & 31;
    const int g = lane >> 2, tig = lane & 3;
    const int bh = blockIdx.y;
    const int r0 = blockIdx.x * 128;
    const size_t cb = (size_t)bh * 128 * NPIX;

#pragma unroll
    for (int i = 0; i < 2; i++) {
        int idx = i * 256 + tid;
        int row = idx >> 4, ch = idx & 15;
        cpa(sb + OFF_Q + row * RS + ch * 16, qv + cb + (size_t)row * NPIX + r0 + ch * 8);
    }
    auto loadK = [&](int mt, int kb) {
#pragma unroll
        for (int i = 0; i < 2; i++) {
            int idx = i * 256 + tid;
            int row = idx >> 4, ch = idx & 15;
            cpa(sb + OFF_K + kb * KBUF + row * RS + ch * 16,
                qv + cb + (size_t)(32 + row) * NPIX + mt * 128 + ch * 8);
        }
    };
    auto loadV = [&](int mt, int vb) {
#pragma unroll
        for (int i = 0; i < 4; i++) {
            int idx = i * 256 + tid;
            int row = (idx >> 4) & 63, ch = idx & 15;
            cpa(sb + OFF_V + vb * VBUF + row * RS + ch * 16,
                qv + cb + (size_t)(64 + row) * NPIX + mt * 128 + ch * 8);
        }
    };
    loadK(0, 0); loadV(0, 0);
    asm volatile("cp.async.commit_group;");

    float m_s[2] = {-1e30f, -1e30f}, l_s[2] = {0.f, 0.f};
    float accO[8][4];
#pragma unroll
    for (int nt = 0; nt < 8; nt++)
#pragma unroll
        for (int q = 0; q < 4; q++) accO[nt][q] = 0.f;

    const int krow = (lane & 7) + ((lane >> 4) << 3);
    const int mcol = ((lane >> 3) & 1) * 8;
    const int ncsel = lane >> 4;
    const int vrow = ((lane >> 4) << 3) + (lane & 7);
    const int vch  = ((lane >> 3) & 1) * 8;

    uint32_t qf[2][4];

    for (int mt = 0; mt < 8; mt++) {
        asm volatile("cp.async.wait_group 0;");
        __syncthreads();
        const int kb = mt & 1, vb = mt & 1;

        if (mt + 1 < 8) {
            loadK(mt + 1, kb ^ 1);
            loadV(mt + 1, vb ^ 1);
        }
        asm volatile("cp.async.commit_group;");

        if (mt == 0) {
#pragma unroll
            for (int kc = 0; kc < 2; kc++)
                ldsm_x4t(qf[kc], sb + OFF_Q + (kc * 16 + krow) * RS +
                                 (warp * 16 + mcol) * 2);
        }

        float accS[16][4];
#pragma unroll
        for (int fn = 0; fn < 16; fn++)
#pragma unroll
            for (int q = 0; q < 4; q++) accS[fn][q] = 0.f;

#pragma unroll
        for (int kc = 0; kc < 2; kc++) {
#pragma unroll
            for (int fnp = 0; fnp < 8; fnp++) {
                const int ncb = fnp * 2 + ncsel;
                uint32_t bd = sb + OFF_K + kb * KBUF +
                              (uint32_t)(kc * 16 + (lane & 15)) * RS + ncb * 16;
                uint32_t k4[4];
                ldsm_x4t(k4, bd);
                mma_f16(accS[2 * fnp],     qf[kc], k4);
                mma_f16(accS[2 * fnp + 1], qf[kc], k4 + 2);
            }
        }

        float mx0 = -1e30f, mx1 = -1e30f;
#pragma unroll
        for (int fn = 0; fn < 16; fn++) {
            mx0 = fmaxf(mx0, fmaxf(accS[fn][0], accS[fn][1]));
            mx1 = fmaxf(mx1, fmaxf(accS[fn][2], accS[fn][3]));
        }
        mx0 = fmaxf(mx0, __shfl_xor_sync(0xffffffffu, mx0, 1));
        mx0 = fmaxf(mx0, __shfl_xor_sync(0xffffffffu, mx0, 2));
        mx1 = fmaxf(mx1, __shfl_xor_sync(0xffffffffu, mx1, 1));
        mx1 = fmaxf(mx1, __shfl_xor_sync(0xffffffffu, mx1, 2));
        mx0 *= SCALE_ATT; mx1 *= SCALE_ATT;
        mx0 = fmaxf(mx0, m_s[0]);
        mx1 = fmaxf(mx1, m_s[1]);
        const float sf0 = __expf(m_s[0] - mx0);
        const float sf1 = __expf(m_s[1] - mx1);
        m_s[0] = mx0; m_s[1] = mx1;
        l_s[0] *= sf0; l_s[1] *= sf1;
#pragma unroll
        for (int nt = 0; nt < 8; nt++) {
            accO[nt][0] *= sf0; accO[nt][1] *= sf0;
            accO[nt][2] *= sf1; accO[nt][3] *= sf1;
        }

        float ps0 = 0.f, ps1 = 0.f;
#pragma unroll
        for (int fn = 0; fn < 16; fn++) {
            float t0 = fmaf(accS[fn][0], SCALE_ATT, -mx0);
            float t1 = fmaf(accS[fn][1], SCALE_ATT, -mx0);
            float t2 = fmaf(accS[fn][2], SCALE_ATT, -mx1);
            float t3 = fmaf(accS[fn][3], SCALE_ATT, -mx1);
            __half2 ha = h2exp(__floats2half2_rn(t0, t1));
            __half2 hb = h2exp(__floats2half2_rn(t2, t3));
            float2 fa = __half22float2(ha);
            float2 fb = __half22float2(hb);
            ps0 += fa.x + fa.y; ps1 += fb.x + fb.y;
            accS[fn][0] = __uint_as_float(*(uint32_t*)&ha);
            accS[fn][2] = __uint_as_float(*(uint32_t*)&hb);
        }
        ps0 += __shfl_xor_sync(0xffffffffu, ps0, 1);
        ps0 += __shfl_xor_sync(0xffffffffu, ps0, 2);
        ps1 += __shfl_xor_sync(0xffffffffu, ps1, 1);
        ps1 += __shfl_xor_sync(0xffffffffu, ps1, 2);
        l_s[0] += ps0; l_s[1] += ps1;

#pragma unroll
        for (int kc = 0; kc < 8; kc++) {
            uint32_t pa[4];
            pa[0] = __float_as_uint(accS[2 * kc][0]);
            pa[1] = __float_as_uint(accS[2 * kc][2]);
            pa[2] = __float_as_uint(accS[2 * kc + 1][0]);
            pa[3] = __float_as_uint(accS[2 * kc + 1][2]);
#pragma unroll
            for (int ntp = 0; ntp < 4; ntp++) {
                uint32_t bd = sb + OFF_V + vb * VBUF +
                              (uint32_t)(ntp * 16 + vrow) * RS + (kc * 16 + vch) * 2;
                uint32_t v4[4];
                ldsm_x4(v4, bd);
                mma_f16(accO[2 * ntp],     pa, v4);
                mma_f16(accO[2 * ntp + 1], pa, v4 + 2);
            }
        }
    }

    const float il0 = 1.0f / l_s[0], il1 = 1.0f / l_s[1];
    const int r = r0 + warp * 16 + g;
#pragma unroll
    for (int nt = 0; nt < 8; nt++) {
        const int d = nt * 8 + 2 * tig;
        xa[(size_t)(bh * 64 + d) * NPIX + r]         = __float2half_rn(accO[nt][0] * il0);
        xa[(size_t)(bh * 64 + d + 1) * NPIX + r]     = __float2half_rn(accO[nt][1] * il0);
        xa[(size_t)(bh * 64 + d) * NPIX + r + 8]     = __float2half_rn(accO[nt][2] * il1);
        xa[(size_t)(bh * 64 + d + 1) * NPIX + r + 8] = __float2half_rn(accO[nt][3] * il1);
    }
}

// ---------------- depthwise 3x3 PE: 4 channels/block, xa += conv(v) in place ----------------
__global__ __launch_bounds__(256) void dwconv_pe(
    const __half* __restrict__ qv, const float* __restrict__ Wpe,
    const float* __restrict__ s, const float* __restrict__ bi,
    __half* __restrict__ xa)
{
    __shared__ float t[4][34 * 34];
    const int c0 = blockIdx.x * 4;
    const int b  = blockIdx.y;
    const int tid = threadIdx.x;

#pragma unroll
    for (int j = 0; j < 4; j++)
        for (int i = tid; i < 34 * 34; i += 256) t[j][i] = 0.0f;
    __syncthreads();
#pragma unroll
    for (int j = 0; j < 4; j++) {
        const int c = c0 + j;
        const int qc = ((c >> 6) * 128) + 64 + (c & 63);
        const __half* src = qv + ((size_t)b * 512 + qc) * NPIX;
        for (int i = tid; i < NPIX; i += 256) {
            int y = i >> 5, x = i & 31;
            t[j][(y + 1) * 34 + (x + 1)] = __half2float(src[i]);
        }
    }
    __syncthreads();

#pragma unroll
    for (int j = 0; j < 4; j++) {
        const int c = c0 + j;
        float w[9];
#pragma unroll
        for (int i = 0; i < 9; i++) w[i] = Wpe[c * 9 + i];
        const float scv = s[c], bv = bi[c];
        __half* dst = xa + ((size_t)b * 256 + c) * NPIX;
        for (int i = tid; i < NPIX; i += 256) {
            int y = i >> 5, x = i & 31;
            float acc = 0.0f;
#pragma unroll
            for (int ky = 0; ky < 3; ky++)
#pragma unroll
                for (int kx = 0; kx < 3; kx++)
                    acc += w[ky * 3 + kx] * t[j][(y + ky) * 34 + (x + kx)];
            float v = __half2float(dst[i]) + acc * scv + bv;
            dst[i] = __float2half_rn(v);
        }
    }
}

// ---------------- launcher ----------------
extern "C" void kernel_launch(void* const* d_in, const int* in_sizes, int n_in,
                              void* d_out, int out_size)
{
    (void)in_sizes; (void)n_in; (void)out_size;
    const float* x      = (const float*)d_in[0];
    const float* W_cv1  = (const float*)d_in[1];
    const float* s_cv1  = (const float*)d_in[2];
    const float* b_cv1  = (const float*)d_in[3];
    const float* W_qkv  = (const float*)d_in[4];
    const float* s_qkv  = (const float*)d_in[5];
    const float* b_qkv  = (const float*)d_in[6];
    const float* W_proj = (const float*)d_in[7];
    const float* s_proj = (const float*)d_in[8];
    const float* b_proj = (const float*)d_in[9];
    const float* W_pe   = (const float*)d_in[10];
    const float* s_pe   = (const float*)d_in[11];
    const float* b_pe   = (const float*)d_in[12];
    const float* W_ffn1 = (const float*)d_in[13];
    const float* s_ffn1 = (const float*)d_in[14];
    const float* b_ffn1 = (const float*)d_in[15];
    const float* W_ffn2 = (const float*)d_in[16];
    const float* s_ffn2 = (const float*)d_in[17];
    const float* b_ffn2 = (const float*)d_in[18];
    const float* W_cv2  = (const float*)d_in[19];
    const float* s_cv2  = (const float*)d_in[20];
    const float* b_cv2  = (const float*)d_in[21];

    static __half *x16 = nullptr, *c16, *t16, *a16, *wh;
    static float *bbf;
    if (!x16) {
        cudaGetSymbolAddress((void**)&x16, g_x16);
        cudaGetSymbolAddress((void**)&c16, g_c16);
        cudaGetSymbolAddress((void**)&t16, g_t16);
        cudaGetSymbolAddress((void**)&a16, g_a16);
        cudaGetSymbolAddress((void**)&wh,  g_wh);
        cudaGetSymbolAddress((void**)&bbf, g_bbf);
        cudaFuncSetAttribute(attn_mma,
                             cudaFuncAttributeMaxDynamicSharedMemorySize, ASMEM);
        cudaFuncSetAttribute(gemm_f16,
                             cudaFuncAttributeMaxDynamicSharedMemorySize, GSMEM);
    }
    float* out = (float*)d_out;
    const long S512 = 512 * NPIX, S256 = 256 * NPIX;

    const int W_CV1 = 0, W_QKV = 262144, W_PROJ = 393216,
              W_FFN1 = 458752, W_FFN2 = 589824, W_CV2 = 720896;

    // #0: convert x + all weights -> fp16 (8192 + 960 = 9152 blocks)
    cvt_all<<<9152, 256>>>(x, W_cv1, W_qkv, W_proj, W_ffn1, W_ffn2, W_cv2, x16, wh);
    // #1: cv1 (SiLU) -> c16 fp16 + bbf f32 for ch>=256
    gemm_f16<<<dim3(8, 4, BSZ), 256, GSMEM>>>(
        x16, S512, 512, wh + W_CV1, s_cv1, b_cv1,
        nullptr, 0, bbf, S256, 256, c16, S512, 1);
    // #2: qkv -> t16 fp16
    gemm_f16<<<dim3(8, 4, BSZ), 256, GSMEM>>>(
        c16 + S256, S512, 256, wh + W_QKV, s_qkv, b_qkv,
        nullptr, 0, nullptr, 0, 1 << 30, t16, S512, 0);
    // #3: flash attention -> a16 (fp16)
    attn_mma<<<dim3(8, 64), 256, ASMEM>>>(t16, a16);
    // #4: PE dwconv: a16 += conv(v) (in place, 4 ch/block)
    dwconv_pe<<<dim3(64, BSZ), 256>>>(t16, W_pe, s_pe, b_pe, a16);
    // #5: proj (+bb residual) -> bbf (in place) + c16 ch256+
    gemm_f16<<<dim3(8, 2, BSZ), 256, GSMEM>>>(
        a16, S256, 256, wh + W_PROJ, s_proj, b_proj,
        bbf, S256, bbf, S256, 0, c16 + S256, S512, 0);
    // #6: ffn1 (SiLU) -> t16
    gemm_f16<<<dim3(8, 4, BSZ), 256, GSMEM>>>(
        c16 + S256, S512, 256, wh + W_FFN1, s_ffn1, b_ffn1,
        nullptr, 0, nullptr, 0, 1 << 30, t16, S512, 1);
    // #7: ffn2 (+bb2 residual) -> c16 ch256+
    gemm_f16<<<dim3(8, 2, BSZ), 256, GSMEM>>>(
        t16, S512, 512, wh + W_FFN2, s_ffn2, b_ffn2,
        bbf, S256, nullptr, 0, 1 << 30, c16 + S256, S512, 0);
    // #8: cv2 (SiLU) -> out
    gemm_f16<<<dim3(8, 4, BSZ), 256, GSMEM>>>(
        c16, S512, 512, wh + W_CV2, s_cv2, b_cv2,
        nullptr, 0, out, S512, 0, nullptr, 0, 1);
}

// round 17
// speedup vs baseline: 1.0375x; 1.0214x over previous
#include <cuda_runtime.h>
#include <cuda_fp16.h>
#include <cstdint>

#define BSZ 16
#define NPIX 1024
#define SCALE_ATT 0.17677669529663687f

// ---------------- static scratch ----------------
__device__ __align__(16) __half g_x16[BSZ * 512 * NPIX];   // input x fp16
__device__ __align__(16) __half g_c16[BSZ * 512 * NPIX];   // cat [a|bb] fp16
__device__ __align__(16) __half g_t16[BSZ * 512 * NPIX];   // qkv / ffn1 fp16
__device__ __align__(16) __half g_a16[BSZ * 256 * NPIX];   // xa fp16 (attn out, then +pe)
__device__ __align__(16) float g_bbf [BSZ * 256 * NPIX];   // bb chain f32 (cm)
__device__ __align__(16) __half g_wh[983040];

__device__ __forceinline__ float silu_f(float v) {
    return v / (1.0f + __expf(-v));
}

__device__ __forceinline__ uint32_t s2u(const void* p) {
    uint32_t a;
    asm("{ .reg .u64 t; cvta.to.shared.u64 t, %1; cvt.u32.u64 %0, t; }" : "=r"(a) : "l"(p));
    return a;
}

__device__ __forceinline__ void cpa(uint32_t saddr, const void* g) {
    asm volatile("cp.async.cg.shared.global [%0], [%1], 16;" :: "r"(saddr), "l"(g));
}

__device__ __forceinline__ void ldsm_x4(uint32_t* r, uint32_t addr) {
    asm volatile("ldmatrix.sync.aligned.m8n8.x4.shared.b16 {%0,%1,%2,%3}, [%4];"
                 : "=r"(r[0]), "=r"(r[1]), "=r"(r[2]), "=r"(r[3]) : "r"(addr));
}

__device__ __forceinline__ void ldsm_x4t(uint32_t* r, uint32_t addr) {
    asm volatile("ldmatrix.sync.aligned.m8n8.x4.trans.shared.b16 {%0,%1,%2,%3}, [%4];"
                 : "=r"(r[0]), "=r"(r[1]), "=r"(r[2]), "=r"(r[3]) : "r"(addr));
}

__device__ __forceinline__ void mma_f16(float* c, const uint32_t* a, const uint32_t* b) {
    asm volatile(
        "mma.sync.aligned.m16n8k16.row.col.f32.f16.f16.f32 "
        "{%0,%1,%2,%3}, {%4,%5,%6,%7}, {%8,%9}, {%0,%1,%2,%3};\n"
        : "+f"(c[0]), "+f"(c[1]), "+f"(c[2]), "+f"(c[3])
        : "r"(a[0]), "r"(a[1]), "r"(a[2]), "r"(a[3]), "r"(b[0]), "r"(b[1]));
}

// ---------------- fp16 tensor-core GEMM (plain W/X, BK=32, 3-stage) ----------------
#define A_BYTES (128 * 80)                   // 10240
#define B_BYTES (32 * 256)                   // 8192
#define STAGE_B (A_BYTES + B_BYTES)          // 18432
#define GSMEM   (3 * STAGE_B)                // 55296

__global__ __launch_bounds__(256, 2) void gemm_f16(
    const __half* __restrict__ X, long xbs, int K,
    const __half* __restrict__ W,
    const float* __restrict__ sc, const float* __restrict__ bi,
    const float* __restrict__ res, long rbs,
    float* __restrict__ outf, long ofbs, int ofoff,
    __half* __restrict__ oh, long ohbs,
    int act)
{
    extern __shared__ __align__(16) char smem[];
    const uint32_t sb = s2u(smem);
    const int tid  = threadIdx.x;
    const int warp = tid >> 5;
    const int lane = tid & 31;
    const int g    = lane >> 2;
    const int tig  = lane & 3;
    const int wm   = warp >> 2;
    const int wn   = warp & 3;
    const int b  = blockIdx.z;
    const int n0 = blockIdx.x * 128;
    const int m0 = blockIdx.y * 128;

    const __half* Xb = X + (size_t)b * xbs;

    float acc[4][4][4];
#pragma unroll
    for (int f = 0; f < 4; f++)
#pragma unroll
        for (int fn = 0; fn < 4; fn++)
#pragma unroll
            for (int q = 0; q < 4; q++) acc[f][fn][q] = 0.0f;

    auto issue = [&](int c, int buf) {
        const uint32_t st = sb + buf * STAGE_B;
        const int k0 = c * 32;
#pragma unroll
        for (int r = 0; r < 2; r++) {
            const int ca  = tid + 256 * r;
            const int row = ca >> 2, kc16 = ca & 3;
            cpa(st + row * 80 + kc16 * 16, W + (size_t)(m0 + row) * K + k0 + kc16 * 8);
        }
#pragma unroll
        for (int r = 0; r < 2; r++) {
            const int ca = tid + 256 * r;
            const int kr = ca >> 4, nc2 = ca & 15;
            cpa(st + A_BYTES + kr * 256 + (((uint32_t)(nc2 ^ (kr & 7))) << 4),
                Xb + (size_t)(k0 + kr) * NPIX + n0 + nc2 * 8);
        }
        asm volatile("cp.async.commit_group;");
    };

    const int nc = K >> 5;
    issue(0, 0);
    if (nc > 1) issue(1, 1);

    const int arow  = wm * 64 + (lane & 15);
    const int akoff = (lane >> 4) * 16;
    const int blk16 = lane & 15;
    const int ncsel = lane >> 4;

    int buf = 0;
    for (int c = 0; c < nc; c++) {
        if (c + 1 < nc) asm volatile("cp.async.wait_group 1;");
        else            asm volatile("cp.async.wait_group 0;");
        __syncthreads();

        const uint32_t st = sb + buf * STAGE_B;

#pragma unroll
        for (int kc = 0; kc < 2; kc++) {
            uint32_t a_h[4][4];
#pragma unroll
            for (int f = 0; f < 4; f++)
                ldsm_x4(a_h[f], st + (uint32_t)(arow + f * 16) * 80 + kc * 32 + akoff);
#pragma unroll
            for (int fnp = 0; fnp < 2; fnp++) {
                const int ncb = wn * 4 + fnp * 2 + ncsel;
                const uint32_t bd = st + A_BYTES + (uint32_t)(kc * 16 + blk16) * 256 +
                                    (((uint32_t)(ncb ^ (blk16 & 7))) << 4);
                uint32_t b4[4];
                ldsm_x4t(b4, bd);
#pragma unroll
                for (int f = 0; f < 4; f++) {
                    mma_f16(acc[f][2 * fnp],     a_h[f], b4);
                    mma_f16(acc[f][2 * fnp + 1], a_h[f], b4 + 2);
                }
            }
            if (kc == 0 && c + 2 < nc) {
                int nb = buf + 2; if (nb >= 3) nb -= 3;
                issue(c + 2, nb);
            }
        }
        if (++buf == 3) buf = 0;
    }

    const bool do_f = (outf != nullptr) && (m0 >= ofoff);
#pragma unroll
    for (int f = 0; f < 4; f++) {
        const int m = m0 + wm * 64 + f * 16 + g;
        const float s0 = sc[m],     b0 = bi[m];
        const float s1 = sc[m + 8], b1 = bi[m + 8];
#pragma unroll
        for (int fn = 0; fn < 4; fn++) {
            const int n = n0 + wn * 32 + fn * 8 + 2 * tig;
            float v00 = acc[f][fn][0] * s0 + b0;
            float v01 = acc[f][fn][1] * s0 + b0;
            float v10 = acc[f][fn][2] * s1 + b1;
            float v11 = acc[f][fn][3] * s1 + b1;
            if (res) {
                float2 ra = *(const float2*)(res + (size_t)b * rbs + (size_t)m * NPIX + n);
                float2 rb = *(const float2*)(res + (size_t)b * rbs + (size_t)(m + 8) * NPIX + n);
                v00 += ra.x; v01 += ra.y; v10 += rb.x; v11 += rb.y;
            }
            if (act) {
                v00 = silu_f(v00); v01 = silu_f(v01);
                v10 = silu_f(v10); v11 = silu_f(v11);
            }
            if (do_f) {
                const int mo = m - ofoff;
                *(float2*)(outf + (size_t)b * ofbs + (size_t)mo * NPIX + n) = make_float2(v00, v01);
                *(float2*)(outf + (size_t)b * ofbs + (size_t)(mo + 8) * NPIX + n) = make_float2(v10, v11);
            }
            if (oh) {
                *(__half2*)(oh + (size_t)b * ohbs + (size_t)m * NPIX + n) =
                    __halves2half2(__float2half_rn(v00), __float2half_rn(v01));
                *(__half2*)(oh + (size_t)b * ohbs + (size_t)(m + 8) * NPIX + n) =
                    __halves2half2(__float2half_rn(v10), __float2half_rn(v11));
            }
        }
    }
}

// ---------------- merged convert: x (8192 blocks) + weights (960 blocks) ----------------
__global__ void cvt_all(
    const float* __restrict__ x,
    const float* __restrict__ W0, const float* __restrict__ W1,
    const float* __restrict__ W2, const float* __restrict__ W3,
    const float* __restrict__ W4, const float* __restrict__ W5,
    __half* __restrict__ x16, __half* __restrict__ wh)
{
    int blk = blockIdx.x;
    const float* src;
    __half* dst;
    if (blk < 8192) {
        src = x; dst = x16;
    } else {
        blk -= 8192;
        int off;
        if      (blk < 256) { src = W0; off = 0;      }
        else if (blk < 384) { src = W1; off = 262144; blk -= 256; }
        else if (blk < 448) { src = W2; off = 393216; blk -= 384; }
        else if (blk < 576) { src = W3; off = 458752; blk -= 448; }
        else if (blk < 704) { src = W4; off = 589824; blk -= 576; }
        else                { src = W5; off = 720896; blk -= 704; }
        dst = wh + off;
    }
    int i = blk * 256 + threadIdx.x;
    float4 v = ((const float4*)src)[i];
    __half h[4];
    h[0] = __float2half_rn(v.x); h[1] = __float2half_rn(v.y);
    h[2] = __float2half_rn(v.z); h[3] = __float2half_rn(v.w);
    ((uint2*)dst)[i] = *(uint2*)h;
}

// ---------------- tensor-core flash attention (FA2, MMA row-sums) ----------------
#define RS 272
#define OFF_Q 0
#define OFF_K 8704
#define KBUF 8704
#define OFF_V 26112
#define VBUF 17408
#define ASMEM 60928

__global__ __launch_bounds__(256, 2) void attn_mma(
    const __half* __restrict__ qv, __half* __restrict__ xa)
{
    extern __shared__ __align__(16) char smn[];
    const uint32_t sb = s2u(smn);

    const int tid = threadIdx.x;
    const int warp = tid >> 5, lane = tid & 31;
    const int g = lane >> 2, tig = lane & 3;
    const int bh = blockIdx.y;
    const int r0 = blockIdx.x * 128;
    const size_t cb = (size_t)bh * 128 * NPIX;

#pragma unroll
    for (int i = 0; i < 2; i++) {
        int idx = i * 256 + tid;
        int row = idx >> 4, ch = idx & 15;
        cpa(sb + OFF_Q + row * RS + ch * 16, qv + cb + (size_t)row * NPIX + r0 + ch * 8);
    }
    auto loadK = [&](int mt, int kb) {
#pragma unroll
        for (int i = 0; i < 2; i++) {
            int idx = i * 256 + tid;
            int row = idx >> 4, ch = idx & 15;
            cpa(sb + OFF_K + kb * KBUF + row * RS + ch * 16,
                qv + cb + (size_t)(32 + row) * NPIX + mt * 128 + ch * 8);
        }
    };
    auto loadV = [&](int mt, int vb) {
#pragma unroll
        for (int i = 0; i < 4; i++) {
            int idx = i * 256 + tid;
            int row = (idx >> 4) & 63, ch = idx & 15;
            cpa(sb + OFF_V + vb * VBUF + row * RS + ch * 16,
                qv + cb + (size_t)(64 + row) * NPIX + mt * 128 + ch * 8);
        }
    };
    loadK(0, 0); loadV(0, 0);
    asm volatile("cp.async.commit_group;");

    float m_s[2] = {-1e30f, -1e30f};
    float accO[8][4];
#pragma unroll
    for (int nt = 0; nt < 8; nt++)
#pragma unroll
        for (int q = 0; q < 4; q++) accO[nt][q] = 0.f;
    float accL[4] = {0.f, 0.f, 0.f, 0.f};   // row-sums via all-ones MMA

    const int krow = (lane & 7) + ((lane >> 4) << 3);
    const int mcol = ((lane >> 3) & 1) * 8;
    const int ncsel = lane >> 4;
    const int vrow = ((lane >> 4) << 3) + (lane & 7);
    const int vch  = ((lane >> 3) & 1) * 8;

    uint32_t qf[2][4];
    const uint32_t ONES2[2] = {0x3C003C00u, 0x3C003C00u};  // half2(1,1) x2

    for (int mt = 0; mt < 8; mt++) {
        asm volatile("cp.async.wait_group 0;");
        __syncthreads();
        const int kb = mt & 1, vb = mt & 1;

        if (mt + 1 < 8) {
            loadK(mt + 1, kb ^ 1);
            loadV(mt + 1, vb ^ 1);
        }
        asm volatile("cp.async.commit_group;");

        if (mt == 0) {
            // Load Q fragments once, pre-scale by SCALE_ATT (fp16)
            const __half2 sc2 = __float2half2_rn(SCALE_ATT);
#pragma unroll
            for (int kc = 0; kc < 2; kc++) {
                ldsm_x4t(qf[kc], sb + OFF_Q + (kc * 16 + krow) * RS +
                                 (warp * 16 + mcol) * 2);
#pragma unroll
                for (int i = 0; i < 4; i++) {
                    __half2 q = __hmul2(*(__half2*)&qf[kc][i], sc2);
                    qf[kc][i] = *(uint32_t*)&q;
                }
            }
        }

        // ---- S = (Q*sc) K^T ----
        float accS[16][4];
#pragma unroll
        for (int fn = 0; fn < 16; fn++)
#pragma unroll
            for (int q = 0; q < 4; q++) accS[fn][q] = 0.f;

#pragma unroll
        for (int kc = 0; kc < 2; kc++) {
#pragma unroll
            for (int fnp = 0; fnp < 8; fnp++) {
                const int ncb = fnp * 2 + ncsel;
                uint32_t bd = sb + OFF_K + kb * KBUF +
                              (uint32_t)(kc * 16 + (lane & 15)) * RS + ncb * 16;
                uint32_t k4[4];
                ldsm_x4t(k4, bd);
                mma_f16(accS[2 * fnp],     qf[kc], k4);
                mma_f16(accS[2 * fnp + 1], qf[kc], k4 + 2);
            }
        }

        // ---- warp-local online softmax (S already scaled) ----
        float mx0 = -1e30f, mx1 = -1e30f;
#pragma unroll
        for (int fn = 0; fn < 16; fn++) {
            mx0 = fmaxf(mx0, fmaxf(accS[fn][0], accS[fn][1]));
            mx1 = fmaxf(mx1, fmaxf(accS[fn][2], accS[fn][3]));
        }
        mx0 = fmaxf(mx0, __shfl_xor_sync(0xffffffffu, mx0, 1));
        mx0 = fmaxf(mx0, __shfl_xor_sync(0xffffffffu, mx0, 2));
        mx1 = fmaxf(mx1, __shfl_xor_sync(0xffffffffu, mx1, 1));
        mx1 = fmaxf(mx1, __shfl_xor_sync(0xffffffffu, mx1, 2));
        mx0 = fmaxf(mx0, m_s[0]);
        mx1 = fmaxf(mx1, m_s[1]);
        const float sf0 = __expf(m_s[0] - mx0);
        const float sf1 = __expf(m_s[1] - mx1);
        m_s[0] = mx0; m_s[1] = mx1;
#pragma unroll
        for (int nt = 0; nt < 8; nt++) {
            accO[nt][0] *= sf0; accO[nt][1] *= sf0;
            accO[nt][2] *= sf1; accO[nt][3] *= sf1;
        }
        accL[0] *= sf0; accL[2] *= sf1;

        // ---- P = exp(S - m) -> fp16 in place (no scalar row-sums) ----
#pragma unroll
        for (int fn = 0; fn < 16; fn++) {
            float t0 = accS[fn][0] - mx0;
            float t1 = accS[fn][1] - mx0;
            float t2 = accS[fn][2] - mx1;
            float t3 = accS[fn][3] - mx1;
            __half2 ha = h2exp(__floats2half2_rn(t0, t1));
            __half2 hb = h2exp(__floats2half2_rn(t2, t3));
            accS[fn][0] = __uint_as_float(*(uint32_t*)&ha);
            accS[fn][2] = __uint_as_float(*(uint32_t*)&hb);
        }

        // ---- O += P V ; L += P 1 (row-sum via all-ones MMA) ----
#pragma unroll
        for (int kc = 0; kc < 8; kc++) {
            uint32_t pa[4];
            pa[0] = __float_as_uint(accS[2 * kc][0]);
            pa[1] = __float_as_uint(accS[2 * kc][2]);
            pa[2] = __float_as_uint(accS[2 * kc + 1][0]);
            pa[3] = __float_as_uint(accS[2 * kc + 1][2]);
            mma_f16(accL, pa, ONES2);
#pragma unroll
            for (int ntp = 0; ntp < 4; ntp++) {
                uint32_t bd = sb + OFF_V + vb * VBUF +
                              (uint32_t)(ntp * 16 + vrow) * RS + (kc * 16 + vch) * 2;
                uint32_t v4[4];
                ldsm_x4(v4, bd);
                mma_f16(accO[2 * ntp],     pa, v4);
                mma_f16(accO[2 * ntp + 1], pa, v4 + 2);
            }
        }
    }

    const float il0 = 1.0f / accL[0], il1 = 1.0f / accL[2];
    const int r = r0 + warp * 16 + g;
#pragma unroll
    for (int nt = 0; nt < 8; nt++) {
        const int d = nt * 8 + 2 * tig;
        xa[(size_t)(bh * 64 + d) * NPIX + r]         = __float2half_rn(accO[nt][0] * il0);
        xa[(size_t)(bh * 64 + d + 1) * NPIX + r]     = __float2half_rn(accO[nt][1] * il0);
        xa[(size_t)(bh * 64 + d) * NPIX + r + 8]     = __float2half_rn(accO[nt][2] * il1);
        xa[(size_t)(bh * 64 + d + 1) * NPIX + r + 8] = __float2half_rn(accO[nt][3] * il1);
    }
}

// ---------------- depthwise 3x3 PE: 4 channels/block, xa += conv(v) in place ----------------
__global__ __launch_bounds__(256) void dwconv_pe(
    const __half* __restrict__ qv, const float* __restrict__ Wpe,
    const float* __restrict__ s, const float* __restrict__ bi,
    __half* __restrict__ xa)
{
    __shared__ float t[4][34 * 34];
    const int c0 = blockIdx.x * 4;
    const int b  = blockIdx.y;
    const int tid = threadIdx.x;

#pragma unroll
    for (int j = 0; j < 4; j++)
        for (int i = tid; i < 34 * 34; i += 256) t[j][i] = 0.0f;
    __syncthreads();
#pragma unroll
    for (int j = 0; j < 4; j++) {
        const int c = c0 + j;
        const int qc = ((c >> 6) * 128) + 64 + (c & 63);
        const __half* src = qv + ((size_t)b * 512 + qc) * NPIX;
        for (int i = tid; i < NPIX; i += 256) {
            int y = i >> 5, x = i & 31;
            t[j][(y + 1) * 34 + (x + 1)] = __half2float(src[i]);
        }
    }
    __syncthreads();

#pragma unroll
    for (int j = 0; j < 4; j++) {
        const int c = c0 + j;
        float w[9];
#pragma unroll
        for (int i = 0; i < 9; i++) w[i] = Wpe[c * 9 + i];
        const float scv = s[c], bv = bi[c];
        __half* dst = xa + ((size_t)b * 256 + c) * NPIX;
        for (int i = tid; i < NPIX; i += 256) {
            int y = i >> 5, x = i & 31;
            float acc = 0.0f;
#pragma unroll
            for (int ky = 0; ky < 3; ky++)
#pragma unroll
                for (int kx = 0; kx < 3; kx++)
                    acc += w[ky * 3 + kx] * t[j][(y + ky) * 34 + (x + kx)];
            float v = __half2float(dst[i]) + acc * scv + bv;
            dst[i] = __float2half_rn(v);
        }
    }
}

// ---------------- launcher ----------------
extern "C" void kernel_launch(void* const* d_in, const int* in_sizes, int n_in,
                              void* d_out, int out_size)
{
    (void)in_sizes; (void)n_in; (void)out_size;
    const float* x      = (const float*)d_in[0];
    const float* W_cv1  = (const float*)d_in[1];
    const float* s_cv1  = (const float*)d_in[2];
    const float* b_cv1  = (const float*)d_in[3];
    const float* W_qkv  = (const float*)d_in[4];
    const float* s_qkv  = (const float*)d_in[5];
    const float* b_qkv  = (const float*)d_in[6];
    const float* W_proj = (const float*)d_in[7];
    const float* s_proj = (const float*)d_in[8];
    const float* b_proj = (const float*)d_in[9];
    const float* W_pe   = (const float*)d_in[10];
    const float* s_pe   = (const float*)d_in[11];
    const float* b_pe   = (const float*)d_in[12];
    const float* W_ffn1 = (const float*)d_in[13];
    const float* s_ffn1 = (const float*)d_in[14];
    const float* b_ffn1 = (const float*)d_in[15];
    const float* W_ffn2 = (const float*)d_in[16];
    const float* s_ffn2 = (const float*)d_in[17];
    const float* b_ffn2 = (const float*)d_in[18];
    const float* W_cv2  = (const float*)d_in[19];
    const float* s_cv2  = (const float*)d_in[20];
    const float* b_cv2  = (const float*)d_in[21];

    static __half *x16 = nullptr, *c16, *t16, *a16, *wh;
    static float *bbf;
    if (!x16) {
        cudaGetSymbolAddress((void**)&x16, g_x16);
        cudaGetSymbolAddress((void**)&c16, g_c16);
        cudaGetSymbolAddress((void**)&t16, g_t16);
        cudaGetSymbolAddress((void**)&a16, g_a16);
        cudaGetSymbolAddress((void**)&wh,  g_wh);
        cudaGetSymbolAddress((void**)&bbf, g_bbf);
        cudaFuncSetAttribute(attn_mma,
                             cudaFuncAttributeMaxDynamicSharedMemorySize, ASMEM);
        cudaFuncSetAttribute(gemm_f16,
                             cudaFuncAttributeMaxDynamicSharedMemorySize, GSMEM);
    }
    float* out = (float*)d_out;
    const long S512 = 512 * NPIX, S256 = 256 * NPIX;

    const int W_CV1 = 0, W_QKV = 262144, W_PROJ = 393216,
              W_FFN1 = 458752, W_FFN2 = 589824, W_CV2 = 720896;

    // #0: convert x + all weights -> fp16
    cvt_all<<<9152, 256>>>(x, W_cv1, W_qkv, W_proj, W_ffn1, W_ffn2, W_cv2, x16, wh);
    // #1: cv1 (SiLU) -> c16 fp16 + bbf f32 for ch>=256
    gemm_f16<<<dim3(8, 4, BSZ), 256, GSMEM>>>(
        x16, S512, 512, wh + W_CV1, s_cv1, b_cv1,
        nullptr, 0, bbf, S256, 256, c16, S512, 1);
    // #2: qkv -> t16 fp16
    gemm_f16<<<dim3(8, 4, BSZ), 256, GSMEM>>>(
        c16 + S256, S512, 256, wh + W_QKV, s_qkv, b_qkv,
        nullptr, 0, nullptr, 0, 1 << 30, t16, S512, 0);
    // #3: flash attention -> a16 (fp16)
    attn_mma<<<dim3(8, 64), 256, ASMEM>>>(t16, a16);
    // #4: PE dwconv: a16 += conv(v) (in place, 4 ch/block)
    dwconv_pe<<<dim3(64, BSZ), 256>>>(t16, W_pe, s_pe, b_pe, a16);
    // #5: proj (+bb residual) -> bbf (in place) + c16 ch256+
    gemm_f16<<<dim3(8, 2, BSZ), 256, GSMEM>>>(
        a16, S256, 256, wh + W_PROJ, s_proj, b_proj,
        bbf, S256, bbf, S256, 0, c16 + S256, S512, 0);
    // #6: ffn1 (SiLU) -> t16
    gemm_f16<<<dim3(8, 4, BSZ), 256, GSMEM>>>(
        c16 + S256, S512, 256, wh + W_FFN1, s_ffn1, b_ffn1,
        nullptr, 0, nullptr, 0, 1 << 30, t16, S512, 1);
    // #7: ffn2 (+bb2 residual) -> c16 ch256+
    gemm_f16<<<dim3(8, 2, BSZ), 256, GSMEM>>>(
        t16, S512, 512, wh + W_FFN2, s_ffn2, b_ffn2,
        bbf, S256, nullptr, 0, 1 << 30, c16 + S256, S512, 0);
    // #8: cv2 (SiLU) -> out
    gemm_f16<<<dim3(8, 4, BSZ), 256, GSMEM>>>(
        c16, S512, 512, wh + W_CV2, s_cv2, b_cv2,
        nullptr, 0, out, S512, 0, nullptr, 0, 1);
}